// round 8
// baseline (speedup 1.0000x reference)
#include <cuda_runtime.h>
#include <cuda_bf16.h>
#include <cstdint>

// FWHT-4096 / sqrt(4096). R4 bit-group schedule (proven conflict-free, affine
// addressing) + persistent CTAs with cp.async (LDGSTS) smem prefetch of the
// next row: zero register cost, DRAM read stream stays busy through the
// smem/FADD phases.
//
// Index i = Q*1024 + P*128 + D*32 + L  (Q:i[10:12], P:i[7:10], D:i[5:7], L:i[0:5])
// Round 1: H32 over (Q,P)=i[7:12] in regs  (reads staged row from smem, linear)
// Round 2: H32 over L=i[0:5]      in regs  (padded transpose buffer, conflict-free)
// Round 3: H4  over D=i[5:7]      in regs  (stores: lanes = L, fully coalesced)
// Hadamard bit-stages commute -> equals the reference 12-stage FWHT.

#define FWHT_N 4096
#define ROW_THREADS 128
#define CTAS_PER_SM 6
#define NUM_SMS 152
#define GRID_CTAS (CTAS_PER_SM * NUM_SMS)   // 912 persistent CTAs
// Transpose buffer strides: L:1, D:33(==1%32), P:132(==4%32), Q:1056(==0%32)
#define S_D 33
#define S_P 132
#define S_Q 1056
#define T_FLOATS (4 * S_Q)                  // 4224 floats = 16.9 KB

__device__ __forceinline__ void cp_async16(uint32_t smem_addr, const float4* gptr) {
    asm volatile("cp.async.cg.shared.global [%0], [%1], 16;"
                 :: "r"(smem_addr), "l"(gptr));
}
#define CP_COMMIT() asm volatile("cp.async.commit_group;")
#define CP_WAIT0()  asm volatile("cp.async.wait_group 0;")

__device__ __forceinline__ void h32(float v[32]) {
#pragma unroll
    for (int h = 1; h < 32; h <<= 1) {
#pragma unroll
        for (int i = 0; i < 32; i++) {
            if (!(i & h)) {
                float a = v[i], b = v[i | h];
                v[i]     = a + b;
                v[i | h] = a - b;
            }
        }
    }
}

__global__ void __launch_bounds__(ROW_THREADS, CTAS_PER_SM)
fwht4096_kernel(const float* __restrict__ x, float* __restrict__ out, int nrows) {
    __shared__ float4 stage[FWHT_N / 4];    // 16 KB linear staging (one row)
    __shared__ float  T[T_FLOATS];          // 16.9 KB padded transpose buffer

    const int j = threadIdx.x;
    const int stride = gridDim.x;

    // Per-thread roles (constant across rows)
    const int D1 = j >> 5, L1 = j & 31;                    // W1: thread (D,L)
    const int D2 = j & 3, P2 = (j >> 2) & 7, Q2 = j >> 5;  // R2: thread (Q,P,D)
    const int L3 = j & 31, Q3 = j >> 5;                    // R3: thread (Q,L)

    float* __restrict__ w1       = T + D1 * S_D + L1;
    float* __restrict__ b2       = T + Q2 * S_Q + P2 * S_P + D2 * S_D;
    const float* __restrict__ b3 = T + Q3 * S_Q + L3;
    const float* __restrict__ st = reinterpret_cast<const float*>(stage);

    const uint32_t stage_base =
        (uint32_t)__cvta_generic_to_shared(stage) + (uint32_t)(j * 16);

    int row = blockIdx.x;
    if (row >= nrows) return;

    // Prologue: stage row 0 (8 x 16B per thread; warp = 512B contiguous)
    {
        const float4* __restrict__ g = reinterpret_cast<const float4*>(
            x + (size_t)row * FWHT_N) + j;
#pragma unroll
        for (int k = 0; k < 8; k++)
            cp_async16(stage_base + (uint32_t)(k * ROW_THREADS * 16), g + k * ROW_THREADS);
        CP_COMMIT();
    }

    while (true) {
        CP_WAIT0();
        __syncthreads();   // stage ready; also orders prev R3 T-reads vs this W1

        // ---- Round 1: regs = (Q,P). LDS lanes = j -> conflict-free. ----
        float v[32];
#pragma unroll
        for (int r = 0; r < 32; r++) v[r] = st[r * 128 + j];
        h32(v);            // transforms bits 7..11
#pragma unroll
        for (int r = 0; r < 32; r++) {
            const int Q = r >> 3, P = r & 7;
            w1[Q * S_Q + P * S_P] = v[r];   // lanes vary L -> conflict-free
        }
        __syncthreads();   // stage fully consumed; T populated

        // ---- Kick prefetch of next row into stage (flies under R2/R3/STG) ----
        const int nrow = row + stride;
        const bool pf = (nrow < nrows);
        if (pf) {
            const float4* __restrict__ g = reinterpret_cast<const float4*>(
                x + (size_t)nrow * FWHT_N) + j;
#pragma unroll
            for (int k = 0; k < 8; k++)
                cp_async16(stage_base + (uint32_t)(k * ROW_THREADS * 16), g + k * ROW_THREADS);
            CP_COMMIT();
        }

        // ---- Round 2: H32 over L, in-place on own slots (banks 4P+D+L). ----
        float t[32];
#pragma unroll
        for (int L = 0; L < 32; L++) t[L] = b2[L];
        h32(t);            // transforms bits 0..4
#pragma unroll
        for (int L = 0; L < 32; L++) b2[L] = t[L];
        __syncthreads();

        // ---- Round 3: gather (P,D), H4 over D, coalesced stores. ----
#pragma unroll
        for (int r = 0; r < 32; r++) {
            const int P = r >> 2, D = r & 3;
            t[r] = b3[P * S_P + D * S_D];   // lanes vary L -> conflict-free
        }
#pragma unroll
        for (int h = 1; h < 4; h <<= 1) {
#pragma unroll
            for (int i = 0; i < 32; i++) {
                if (!(i & h)) {
                    float a = t[i], c = t[i | h];
                    t[i]     = a + c;
                    t[i | h] = a - c;
                }
            }
        }
        {
            const float scale = 1.0f / 64.0f;   // 1/sqrt(4096)
            float* __restrict__ o = out + (size_t)row * FWHT_N + Q3 * 1024 + L3;
#pragma unroll
            for (int r = 0; r < 32; r++) {
                const int P = r >> 2, D = r & 3;
                o[P * 128 + D * 32] = t[r] * scale;  // lanes = L -> coalesced
            }
        }

        if (!pf) break;
        row = nrow;
    }
}

extern "C" void kernel_launch(void* const* d_in, const int* in_sizes, int n_in,
                              void* d_out, int out_size) {
    const float* x = (const float*)d_in[0];
    float* out     = (float*)d_out;
    const int nrows = in_sizes[0] / FWHT_N;   // 16384
    const int grid  = (nrows < GRID_CTAS) ? nrows : GRID_CTAS;
    fwht4096_kernel<<<grid, ROW_THREADS>>>(x, out, nrows);
}

// round 9
// speedup vs baseline: 1.1481x; 1.1481x over previous
#include <cuda_runtime.h>
#include <cuda_bf16.h>

// FWHT-4096 / sqrt(4096), fully vectorized global I/O (LDG.128 / STG.128).
// Index i = V*512 + U*128 + M*4 + c  (V:i[9:12], U:i[7:9], M:i[2:7], c:i[0:2])
// Round 1: H32 over (V,c) in regs — 8x LDG.128, warp = 2KB contiguous
// Round 2: H32 over M     in regs — smem transpose, conflict-free
// Round 3: H4  over U     in regs — 8x STG.128, warp = 512B contiguous
// Hadamard bit-stages commute -> equals the reference 12-stage FWHT.
//
// Smem layout: phys(V,U,M,c) = M*129 + V*16 + U*4 + c   (bijective, 4128 floats)
//   W1  (lanes M, U warp-fixed; V,c per instr): banks = M + const      -> CF
//   R2/W2 (thread j reads stride 129; lanes j): banks = j + M          -> CF
//   R3  (lanes M, V12 warp-fixed; r per instr): banks = M + r          -> CF

#define FWHT_N 4096
#define ROW_THREADS 128
#define ROWS_PER_BLOCK 2
#define BLOCK_THREADS (ROW_THREADS * ROWS_PER_BLOCK)
#define S_M 129
#define T_ROW (32 * S_M)          // 4128 floats = 16.5 KB per row

__device__ __forceinline__ void h32(float v[32]) {
#pragma unroll
    for (int h = 1; h < 32; h <<= 1) {
#pragma unroll
        for (int i = 0; i < 32; i++) {
            if (!(i & h)) {
                float a = v[i], b = v[i | h];
                v[i]     = a + b;
                v[i | h] = a - b;
            }
        }
    }
}

__global__ void __launch_bounds__(BLOCK_THREADS, 4)
fwht4096_kernel(const float* __restrict__ x, float* __restrict__ out) {
    __shared__ float T[ROWS_PER_BLOCK * T_ROW];

    const int tid = threadIdx.x;
    const int rib = tid >> 7;                 // row in block
    const int j   = tid & 127;                // thread within row
    const size_t row = (size_t)blockIdx.x * ROWS_PER_BLOCK + rib;

    const float4* __restrict__ x4 = reinterpret_cast<const float4*>(x + row * FWHT_N);
    float4* __restrict__ o4       = reinterpret_cast<float4*>(out + row * FWHT_N);
    float* __restrict__ Tr        = T + rib * T_ROW;

    float v[32];

    // ---- Round 1: regs r = V*4 + c. Load 8 float4s: addr4 = V*128 + j. ----
#pragma unroll
    for (int V = 0; V < 8; V++) {
        float4 t = x4[V * 128 + j];
        v[4 * V + 0] = t.x;
        v[4 * V + 1] = t.y;
        v[4 * V + 2] = t.z;
        v[4 * V + 3] = t.w;
    }
    h32(v);   // H over bits {0,1, 9,10,11}

    // W1: thread (U = j>>5, M = j&31) scatters; offsets V*16 + c per value.
    {
        float* w = Tr + (j & 31) * S_M + (j >> 5) * 4;
#pragma unroll
        for (int r = 0; r < 32; r++) {
            const int V = r >> 2, c = r & 3;
            w[V * 16 + c] = v[r];             // banks = M + (16V+4U+c) -> CF
        }
    }
    __syncthreads();

    // ---- Round 2: thread j owns (V,U,c)=j, all M. Stride-129, in place. ----
    {
        float* b = Tr + j;
#pragma unroll
        for (int M = 0; M < 32; M++) v[M] = b[M * S_M];   // banks = j + M -> CF
        h32(v);   // H over bits 2..6
#pragma unroll
        for (int M = 0; M < 32; M++) b[M * S_M] = v[M];
    }
    __syncthreads();

    // ---- Round 3: thread (V12 = j>>5, M = j&31); regs r = V0*16 + U*4 + c. ----
    {
        const float* b = Tr + (j & 31) * S_M + (j >> 5) * 32;
#pragma unroll
        for (int r = 0; r < 32; r++) v[r] = b[r];         // banks = M + r -> CF

        // H4 over U = bits 2..3 of r (V0, c passengers)
#pragma unroll
        for (int h = 4; h < 16; h <<= 1) {
#pragma unroll
            for (int i = 0; i < 32; i++) {
                if (!(i & h)) {
                    float a = v[i], c2 = v[i | h];
                    v[i]     = a + c2;
                    v[i | h] = a - c2;
                }
            }
        }

        const float scale = 1.0f / 64.0f;     // 1/sqrt(4096)
        // Store: addr4 = (2*V12+V0)*128 + U*32 + M; lanes = M -> 512B contiguous
        float4* __restrict__ o = o4 + (j >> 5) * 256 + (j & 31);
#pragma unroll
        for (int q = 0; q < 8; q++) {         // q = V0*4 + U
            const int V0 = q >> 2, U = q & 3;
            float4 t;
            t.x = v[q * 4 + 0] * scale;
            t.y = v[q * 4 + 1] * scale;
            t.z = v[q * 4 + 2] * scale;
            t.w = v[q * 4 + 3] * scale;
            o[V0 * 128 + U * 32] = t;
        }
    }
}

extern "C" void kernel_launch(void* const* d_in, const int* in_sizes, int n_in,
                              void* d_out, int out_size) {
    const float* x = (const float*)d_in[0];
    float* out     = (float*)d_out;
    const int nrows = in_sizes[0] / FWHT_N;          // 16384
    const int grid  = nrows / ROWS_PER_BLOCK;        // 8192
    fwht4096_kernel<<<grid, BLOCK_THREADS>>>(x, out);
}

// round 10
// speedup vs baseline: 1.1713x; 1.0202x over previous
#include <cuda_runtime.h>
#include <cuda_bf16.h>

// FWHT-4096 / sqrt(4096). R4 bit-group schedule (best measured design) with
// streaming cache policy (ld.global.cs / st.global.cs): both global streams
// have zero reuse, so evict-first keeps the write stream from churning L2
// against the read stream's fills.
//
// Index i = Q*1024 + P*128 + D*32 + L  (Q:i[10:12], P:i[7:10], D:i[5:7], L:i[0:5])
// Round 1: H32 over (Q,P)=i[7:12] in regs  (loads:  lanes = j, ideal coalescing)
// Round 2: H32 over L=i[0:5]      in regs  (smem transpose, conflict-free)
// Round 3: H4  over D=i[5:7]      in regs  (stores: lanes = L, ideal coalescing)
// Hadamard bit-stages commute -> equals the reference 12-stage FWHT.

#define FWHT_N 4096
#define ROW_THREADS 128
#define ROWS_PER_BLOCK 2
#define BLOCK_THREADS (ROW_THREADS * ROWS_PER_BLOCK)
// smem strides: L:1, D:33 (==1 mod 32), P:132 (==4 mod 32), Q:1056 (==0 mod 32)
#define S_D 33
#define S_P 132
#define S_Q 1056
#define S_ROW (4 * S_Q)   // 4224 floats per row (16.9 KB)

__device__ __forceinline__ void h32(float v[32]) {
#pragma unroll
    for (int h = 1; h < 32; h <<= 1) {
#pragma unroll
        for (int i = 0; i < 32; i++) {
            if (!(i & h)) {
                float a = v[i], b = v[i | h];
                v[i]     = a + b;
                v[i | h] = a - b;
            }
        }
    }
}

__global__ void __launch_bounds__(BLOCK_THREADS, 4)
fwht4096_kernel(const float* __restrict__ x, float* __restrict__ out) {
    __shared__ float s[ROWS_PER_BLOCK * S_ROW];

    const int tid = threadIdx.x;
    const int rib = tid >> 7;          // row in block
    const int j   = tid & 127;         // thread within row
    const size_t row = (size_t)blockIdx.x * ROWS_PER_BLOCK + rib;

    const float* __restrict__ xr = x + row * FWHT_N;
    float* __restrict__ orow     = out + row * FWHT_N;
    float* __restrict__ sr       = s + rib * S_ROW;

    float v[32];

    // ---- Round 1: regs = (Q,P). Streaming loads, lanes = j -> one line/warp. ----
#pragma unroll
    for (int r = 0; r < 32; r++) v[r] = __ldcs(xr + r * 128 + j);
    h32(v);   // transforms index bits 7..11

    // W1: thread (D,L) writes (Q,P)-indexed values. Lanes vary L -> conflict-free.
    {
        const int D = j >> 5, L = j & 31;
        float* w = sr + D * S_D + L;
#pragma unroll
        for (int r = 0; r < 32; r++) {
            const int Q = r >> 3, P = r & 7;
            w[Q * S_Q + P * S_P] = v[r];
        }
    }
    __syncthreads();

    // ---- Round 2: regs = L. Thread (Q,P,D): j = Q*32 + P*4 + D. In-place. ----
    {
        const int D = j & 3, P = (j >> 2) & 7, Q = j >> 5;
        float* b = sr + Q * S_Q + P * S_P + D * S_D;
        // banks = 4P + D + L mod 32: lanes (P,D) cover 0..31 -> conflict-free
#pragma unroll
        for (int L = 0; L < 32; L++) v[L] = b[L];
        h32(v);   // transforms index bits 0..4
#pragma unroll
        for (int L = 0; L < 32; L++) b[L] = v[L];
    }
    __syncthreads();

    // ---- Round 3: gather (P,D), H4 over D, streaming coalesced stores. ----
    {
        const int L = j & 31, Q = j >> 5;
        const float* b = sr + Q * S_Q + L;
#pragma unroll
        for (int r = 0; r < 32; r++) {
            const int P = r >> 2, D = r & 3;
            v[r] = b[P * S_P + D * S_D];   // lanes vary L -> conflict-free
        }
#pragma unroll
        for (int h = 1; h < 4; h <<= 1) {
#pragma unroll
            for (int i = 0; i < 32; i++) {
                if (!(i & h)) {
                    float a = v[i], c = v[i | h];
                    v[i]     = a + c;
                    v[i | h] = a - c;
                }
            }
        }
        const float scale = 1.0f / 64.0f;   // 1/sqrt(4096)
        float* o = orow + Q * 1024 + L;
        // store addr = Q*1024 + P*128 + D*32 + L; lanes = L -> fully coalesced
#pragma unroll
        for (int r = 0; r < 32; r++) {
            const int P = r >> 2, D = r & 3;
            __stcs(o + P * 128 + D * 32, v[r] * scale);
        }
    }
}

extern "C" void kernel_launch(void* const* d_in, const int* in_sizes, int n_in,
                              void* d_out, int out_size) {
    const float* x = (const float*)d_in[0];
    float* out     = (float*)d_out;
    const int nrows = in_sizes[0] / FWHT_N;          // 16384
    const int grid  = nrows / ROWS_PER_BLOCK;        // 8192
    fwht4096_kernel<<<grid, BLOCK_THREADS>>>(x, out);
}